// round 3
// baseline (speedup 1.0000x reference)
#include <cuda_runtime.h>

#define BB 64
#define TT 4096
#define HH 128
#define GG 384   /* 3H */

// Handoff buffers (allocation-free rule: __device__ globals)
__device__ float g_h0[(size_t)BB * TT * HH];   // layer-0 outputs, 128 MiB
__device__ int   g_flag[(size_t)BB * TT];      // per-(b,t) ready flags, 1 MiB

typedef unsigned long long ull;

static __device__ __forceinline__ ull pk(float a, float b) {
    ull r; asm("mov.b64 %0, {%1, %2};" : "=l"(r) : "f"(a), "f"(b)); return r;
}
static __device__ __forceinline__ void upk(ull v, float& a, float& b) {
    asm("mov.b64 {%0, %1}, %2;" : "=f"(a), "=f"(b) : "l"(v));
}
// Packed fp32x2 FMA (Blackwell): 2 MACs per issue slot
static __device__ __forceinline__ void ffma2(ull& acc, ull a, ull b) {
    asm("fma.rn.f32x2 %0, %1, %2, %0;" : "+l"(acc) : "l"(a), "l"(b));
}
static __device__ __forceinline__ float red2(ull a, ull b) {
    float x0, x1, y0, y1; upk(a, x0, x1); upk(b, y0, y1);
    return (x0 + x1) + (y0 + y1);
}
static __device__ __forceinline__ float sigf(float x) {
    return __fdividef(1.f, 1.f + __expf(-x));
}
static __device__ __forceinline__ float tanhv(float x) {
    return 2.f * __fdividef(1.f, 1.f + __expf(-2.f * x)) - 1.f;
}
static __device__ __forceinline__ int ldacq(const int* p) {
    int v; asm volatile("ld.acquire.gpu.global.b32 %0, [%1];" : "=r"(v) : "l"(p) : "memory");
    return v;
}
static __device__ __forceinline__ void strel(int* p, int v) {
    asm volatile("st.release.gpu.global.b32 [%0], %1;" :: "l"(p), "r"(v) : "memory");
}

// Load one 128-float weight row into 64 packed register pairs.
static __device__ __forceinline__ void loadw(ull* w, const float* __restrict__ row) {
    const float4* r4 = (const float4*)row;
#pragma unroll
    for (int i = 0; i < 32; i++) {
        float4 v = r4[i];
        w[2 * i]     = pk(v.x, v.y);
        w[2 * i + 1] = pk(v.z, v.w);
    }
}

// dot(w_row[128], hsm[128]) with broadcast LDS.128 + packed FMA, 4 acc chains.
static __device__ __forceinline__ float dot128(const ull* w, const float* hsm) {
    const ulonglong2* h2 = (const ulonglong2*)hsm;
    ull a0 = 0, a1 = 0, a2 = 0, a3 = 0;
#pragma unroll
    for (int k = 0; k < 16; k++) {
        ulonglong2 p = h2[2 * k];
        ulonglong2 q = h2[2 * k + 1];
        ffma2(a0, w[4 * k + 0], p.x);
        ffma2(a1, w[4 * k + 1], p.y);
        ffma2(a2, w[4 * k + 2], q.x);
        ffma2(a3, w[4 * k + 3], q.y);
    }
    return red2(a0, a1) + red2(a2, a3);
}

__global__ void k_reset() {
    size_t i = (size_t)blockIdx.x * 1024 + threadIdx.x;
    if (i < (size_t)BB * TT) g_flag[i] = 0;
}

// Thread layout (both roles): warp=tid>>5, grp=warp/3, role=warp%3 (0=r,1=z,2=n)
// Group g owns hidden units [32g,32g+32); named barrier (g+1) over its 96 threads.
// h double-buffered in SMEM -> one block-wide barrier per timestep.
__global__ void __launch_bounds__(384, 1)
k_pipe(const float* __restrict__ data, const float* __restrict__ hidden,
       const float* __restrict__ w_ih0, const float* __restrict__ w_hh0,
       const float* __restrict__ b_ih0, const float* __restrict__ b_hh0,
       const float* __restrict__ w_ih1, const float* __restrict__ w_hh1,
       const float* __restrict__ b_ih1, const float* __restrict__ b_hh1,
       const float* __restrict__ fc_w, const float* __restrict__ fc_b,
       float* __restrict__ out, float* __restrict__ hT) {
    extern __shared__ __align__(16) float4 w4s[];   // consumer: w_ih1 k-major [32][384]
    __shared__ __align__(16) float h1sm[2][HH];
    __shared__ __align__(16) float h0sm[2][HH];
    __shared__ float s_z[HH], s_hn[HH], s_xn[HH];
    __shared__ __align__(16) float xbuf[512];
    __shared__ float red[2][4];

    const int tid = threadIdx.x;
    const int warp = tid >> 5, lane = tid & 31;
    const int grp = warp / 3, role = warp - grp * 3;
    const int unit = (grp << 5) | lane;
    const int row = role * HH + unit;

    if (blockIdx.x < BB) {
        // ================= PRODUCER: layer-0 recurrence =================
        const int b = blockIdx.x;
        ull w[64];
        loadw(w, w_hh0 + row * HH);
        const float wi = w_ih0[row], bi = b_ih0[row], bh = b_hh0[row];

        float h_old = hidden[(size_t)b * HH + unit];
        if (role == 0) h1sm[0][unit] = h_old;
        __syncthreads();

        const float* xg = data + (size_t)b * TT;
        float* hb = g_h0 + (size_t)b * TT * HH;
        int* fl = g_flag + (size_t)b * TT;

        int cur = 0;
        for (int t = 0; t < TT; t++) {
            if ((t & 511) == 0) {
                if (tid < 128) ((float4*)xbuf)[tid] = ((const float4*)(xg + t))[tid];
                __syncthreads();
            }
            const float x = xbuf[t & 511];
            float acc = dot128(w, h1sm[cur]) + bh;
            float xi = fmaf(x, wi, bi);
            float pre = acc + xi;                   // role 0: r_pre
            if (role == 1) s_z[unit] = pre;
            else if (role == 2) { s_hn[unit] = acc; s_xn[unit] = xi; }
            asm volatile("bar.sync %0, 96;" :: "r"(grp + 1) : "memory");
            if (role == 0) {
                float r = sigf(pre);
                float z = sigf(s_z[unit]);
                float n = tanhv(fmaf(r, s_hn[unit], s_xn[unit]));
                h_old = (1.f - z) * n + z * h_old;
                h1sm[cur ^ 1][unit] = h_old;
                hb[(size_t)t * HH + unit] = h_old;  // ship to consumer
                __threadfence();
            }
            __syncthreads();
            if (tid == 0) strel(fl + t, 1);
            cur ^= 1;
        }
        if (role == 0) hT[(size_t)b * HH + unit] = h_old;
    } else {
        // ========= CONSUMER: layer-1 recurrence + inline ih-dot + FC =========
        const int b = blockIdx.x - BB;
        ull w[64];
        loadw(w, w_hh1 + row * HH);
        const float bh = b_hh1[row], bi = b_ih1[row];
        const float fw = fc_w[unit];
        const float fcb = fc_b[0];

        // Stage w_ih1 into SMEM, k-major: w4s[k4*GG + r] = w_ih1[r][4k4..4k4+3]
        {
            const float4* src = (const float4*)(w_ih1 + (size_t)tid * HH);
#pragma unroll
            for (int k = 0; k < 32; k++) w4s[k * GG + tid] = src[k];
        }

        float h_old = hidden[(size_t)(BB + b) * HH + unit];   // hidden[1][b]
        if (role == 0) h1sm[0][unit] = h_old;

        const float* hb = g_h0 + (size_t)b * TT * HH;
        const int* fl = g_flag + (size_t)b * TT;

        if (warp == 2) {                    // warm h0sm[0]
            while (ldacq(fl) == 0) __nanosleep(32);
            ((float4*)h0sm[0])[lane] = ((const float4*)hb)[lane];
        }
        __syncthreads();

        float* outp = out + (size_t)b * TT;
        int cur = 0;
        float p = 0.f;
        for (int t = 0; t < TT; t++) {
            // Fused dual dot: hh = w_hh1[row]·h1 (regs x bcast LDS),
            //                 ih = w_ih1[row]·h0 (k-major SMEM x bcast LDS)
            const ulonglong2* h1p = (const ulonglong2*)h1sm[cur];
            const ulonglong2* h0p = (const ulonglong2*)h0sm[cur];
            const ulonglong2* wp = (const ulonglong2*)w4s;
            ull a0 = 0, a1 = 0, c0 = 0, c1 = 0;
#pragma unroll
            for (int k = 0; k < 32; k++) {
                ulonglong2 hq = h1p[k];
                ulonglong2 xq = h0p[k];
                ulonglong2 wq = wp[k * GG + row];
                ffma2(a0, w[2 * k], hq.x);
                ffma2(a1, w[2 * k + 1], hq.y);
                ffma2(c0, wq.x, xq.x);
                ffma2(c1, wq.y, xq.y);
            }
            float hh_t = red2(a0, a1) + bh;
            float ih_t = red2(c0, c1) + bi;
            float pre = hh_t + ih_t;                // role 0: r_pre
            if (role == 1) s_z[unit] = pre;
            else if (role == 2) { s_hn[unit] = hh_t; s_xn[unit] = ih_t; }
            asm volatile("bar.sync %0, 96;" :: "r"(grp + 1) : "memory");
            if (role == 0) {
                float r = sigf(pre);
                float z = sigf(s_z[unit]);
                float n = tanhv(fmaf(r, s_hn[unit], s_xn[unit]));
                h_old = (1.f - z) * n + z * h_old;
                h1sm[cur ^ 1][unit] = h_old;
                p = fmaxf(h_old, 0.f) * fw;
            }
            if (warp == 2 && t + 1 < TT) {          // prefetch h0[t+1]
                const int* f1 = fl + t + 1;
                while (ldacq(f1) == 0) __nanosleep(32);
                ((float4*)h0sm[cur ^ 1])[lane] =
                    ((const float4*)(hb + (size_t)(t + 1) * HH))[lane];
            }
            __syncthreads();
            // Branchless butterfly; real p only on role-0 lanes.
            float q = p;
            q += __shfl_xor_sync(0xffffffffu, q, 16);
            q += __shfl_xor_sync(0xffffffffu, q, 8);
            q += __shfl_xor_sync(0xffffffffu, q, 4);
            q += __shfl_xor_sync(0xffffffffu, q, 2);
            q += __shfl_xor_sync(0xffffffffu, q, 1);
            if (role == 0 && lane == 0) red[t & 1][grp] = q;
            if (t > 0 && tid == 0) {
                const float* rd = red[(t - 1) & 1];
                outp[t - 1] = ((rd[0] + rd[1]) + (rd[2] + rd[3])) + fcb;
            }
            cur ^= 1;
        }
        __syncthreads();
        if (tid == 0) {
            const float* rd = red[(TT - 1) & 1];
            outp[TT - 1] = ((rd[0] + rd[1]) + (rd[2] + rd[3])) + fcb;
        }
        if (role == 0) hT[(size_t)BB * HH + (size_t)b * HH + unit] = h_old;
    }
}

extern "C" void kernel_launch(void* const* d_in, const int* in_sizes, int n_in,
                              void* d_out, int out_size) {
    const float* data   = (const float*)d_in[0];
    const float* hidden = (const float*)d_in[1];
    const float* w_ih0  = (const float*)d_in[2];
    const float* w_hh0  = (const float*)d_in[3];
    const float* b_ih0  = (const float*)d_in[4];
    const float* b_hh0  = (const float*)d_in[5];
    const float* w_ih1  = (const float*)d_in[6];
    const float* w_hh1  = (const float*)d_in[7];
    const float* b_ih1  = (const float*)d_in[8];
    const float* b_hh1  = (const float*)d_in[9];
    const float* fc_w   = (const float*)d_in[10];
    const float* fc_b   = (const float*)d_in[11];

    float* out = (float*)d_out;
    float* hT  = out + (size_t)BB * TT;   // [2,B,H] final hidden

    const int smem = 32 * GG * sizeof(float4);   // 196608 B
    cudaFuncSetAttribute(k_pipe, cudaFuncAttributeMaxDynamicSharedMemorySize, smem);

    k_reset<<<(BB * TT + 1023) / 1024, 1024>>>();
    k_pipe<<<2 * BB, 384, smem>>>(data, hidden, w_ih0, w_hh0, b_ih0, b_hh0,
                                  w_ih1, w_hh1, b_ih1, b_hh1, fc_w, fc_b,
                                  out, hT);
}

// round 4
// speedup vs baseline: 1.6301x; 1.6301x over previous
#include <cuda_runtime.h>

#define BB 64
#define TT 4096
#define HH 128
#define GG 384   /* 3H */
#define NWORK 80 /* B-worker CTAs */

// Scratch (allocation-free rule: __device__ globals)
__device__ float g_y0[(size_t)BB * TT * HH];    // [b][t][k]   128 MiB
__device__ float g_xg1[(size_t)BB * TT * GG];   // [b][t][g]   402 MiB
__device__ int   g_flag[BB * 32];               // per-(b, 128-t chunk)

typedef unsigned long long ull;

static __device__ __forceinline__ ull pk(float a, float b) {
    ull r; asm("mov.b64 %0, {%1, %2};" : "=l"(r) : "f"(a), "f"(b)); return r;
}
static __device__ __forceinline__ void upk(ull v, float& a, float& b) {
    asm("mov.b64 {%0, %1}, %2;" : "=f"(a), "=f"(b) : "l"(v));
}
// Packed fp32x2 FMA (Blackwell): 2 MACs per issue slot
static __device__ __forceinline__ void ffma2(ull& acc, ull a, ull b) {
    asm("fma.rn.f32x2 %0, %1, %2, %0;" : "+l"(acc) : "l"(a), "l"(b));
}
static __device__ __forceinline__ float red2(ull a, ull b) {
    float x0, x1, y0, y1; upk(a, x0, x1); upk(b, y0, y1);
    return (x0 + x1) + (y0 + y1);
}
static __device__ __forceinline__ float sigf(float x) {      // exact-ish (z gate)
    return __fdividef(1.f, 1.f + __expf(-x));
}
static __device__ __forceinline__ float tanha(float x) {     // MUFU tanh
    float y; asm("tanh.approx.f32 %0, %1;" : "=f"(y) : "f"(x)); return y;
}
static __device__ __forceinline__ float sigfast(float x) {   // r gate
    return fmaf(0.5f, tanha(0.5f * x), 0.5f);
}
static __device__ __forceinline__ int ldacq(const int* p) {
    int v; asm volatile("ld.acquire.gpu.global.b32 %0, [%1];" : "=r"(v) : "l"(p) : "memory");
    return v;
}
static __device__ __forceinline__ void strel(int* p, int v) {
    asm volatile("st.release.gpu.global.b32 [%0], %1;" :: "l"(p), "r"(v) : "memory");
}

// Load one 128-float weight row into 64 packed register pairs.
static __device__ __forceinline__ void loadw(ull* w, const float* __restrict__ row) {
    const float4* r4 = (const float4*)row;
#pragma unroll
    for (int i = 0; i < 32; i++) {
        float4 v = r4[i];
        w[2 * i]     = pk(v.x, v.y);
        w[2 * i + 1] = pk(v.z, v.w);
    }
}

// dot(w_row[128], hsm[128]) with broadcast LDS.128 + packed FMA, 4 acc chains.
static __device__ __forceinline__ float dot128(const ull* w, const float* hsm) {
    const ulonglong2* h2 = (const ulonglong2*)hsm;
    ull a0 = 0, a1 = 0, a2 = 0, a3 = 0;
#pragma unroll
    for (int k = 0; k < 16; k++) {
        ulonglong2 p = h2[2 * k];
        ulonglong2 q = h2[2 * k + 1];
        ffma2(a0, w[4 * k + 0], p.x);
        ffma2(a1, w[4 * k + 1], p.y);
        ffma2(a2, w[4 * k + 2], q.x);
        ffma2(a3, w[4 * k + 3], q.y);
    }
    return red2(a0, a1) + red2(a2, a3);
}

__global__ void k_reset() {
    int i = blockIdx.x * 1024 + threadIdx.x;
    if (i < BB * 32) g_flag[i] = 0;
}

// ===== Fused phase A+B: 64 producer CTAs (layer-0) + 80 B-worker CTAs =====
// Thread layout (producer): warp=tid>>5, grp=warp/3, role=warp%3 (0=r,1=z,2=n)
// Group g owns hidden units [32g,32g+32); named barrier (g+1) over its 96 threads.
// h double-buffered in SMEM -> one block-wide barrier per timestep.
__global__ void __launch_bounds__(384, 1)
k_phaseAB(const float* __restrict__ data, const float* __restrict__ hidden,
          const float* __restrict__ w_ih0, const float* __restrict__ w_hh0,
          const float* __restrict__ b_ih0, const float* __restrict__ b_hh0,
          const float* __restrict__ w_ih1, const float* __restrict__ b_ih1,
          float* __restrict__ hT) {
    __shared__ __align__(16) float hsm[2][HH];
    __shared__ float s_z[HH], s_hn[HH], s_xn[HH];
    __shared__ __align__(16) float xbuf[512];
    __shared__ __align__(16) float ybuf[8 * HH];

    const int tid = threadIdx.x;

    if (blockIdx.x < BB) {
        // ---------------- PRODUCER: layer-0 recurrence ----------------
        const int warp = tid >> 5, lane = tid & 31;
        const int grp = warp / 3, role = warp - grp * 3;
        const int unit = (grp << 5) | lane;
        const int row = role * HH + unit;
        const int b = blockIdx.x;

        ull w[64];
        loadw(w, w_hh0 + row * HH);
        const float wi = w_ih0[row], bi = b_ih0[row], bh = b_hh0[row];

        float h_old = hidden[(size_t)b * HH + unit];
        if (role == 0) hsm[0][unit] = h_old;
        __syncthreads();

        const float* xg = data + (size_t)b * TT;
        float* y0 = g_y0 + (size_t)b * TT * HH;
        int* fl = g_flag + b * 32;

        int cur = 0;
        for (int t = 0; t < TT; t++) {
            if ((t & 511) == 0) {
                if (tid < 128) ((float4*)xbuf)[tid] = ((const float4*)(xg + t))[tid];
                __syncthreads();
            }
            const float x = xbuf[t & 511];
            float acc = dot128(w, hsm[cur]) + bh;
            float xi = fmaf(x, wi, bi);
            float pre = acc + xi;                   // role 0: r_pre
            if (role == 1) s_z[unit] = pre;
            else if (role == 2) { s_hn[unit] = acc; s_xn[unit] = xi; }
            asm volatile("bar.sync %0, 96;" :: "r"(grp + 1) : "memory");
            if (role == 0) {
                float r = sigfast(pre);
                float z = sigf(s_z[unit]);
                float n = tanha(fmaf(r, s_hn[unit], s_xn[unit]));
                h_old = (1.f - z) * n + z * h_old;
                hsm[cur ^ 1][unit] = h_old;
                y0[(size_t)t * HH + unit] = h_old;  // ship to B-workers
            }
            __syncthreads();
            // chunk-granular publish: barrier + cumulative release => visible
            if (((t & 127) == 127) && tid == 0) strel(fl + (t >> 7), 1);
            cur ^= 1;
        }
        if (role == 0) hT[(size_t)b * HH + unit] = h_old;
    } else {
        // ---------------- B-WORKER: xg1 = y0 @ w_ih1.T + b_ih1 ----------------
        const int wk = blockIdx.x - BB;
        ull w[64];
        loadw(w, w_ih1 + tid * HH);
        const float bi = b_ih1[tid];

        for (int task = wk; task < BB * 32; task += NWORK) {
            const int c = task >> 6, b = task & 63;   // chunk-major: fresh y0 in L2
            if (tid == 0) {
                const int* f = g_flag + b * 32 + c;
                while (ldacq(f) == 0) __nanosleep(64);
            }
            __syncthreads();
            const float* y0 = g_y0 + ((size_t)b * TT + (size_t)c * 128) * HH;
            float* xo = g_xg1 + ((size_t)b * TT + (size_t)c * 128) * GG;
            for (int tt = 0; tt < 128; tt += 8) {
                if (tid < 256) ((float4*)ybuf)[tid] = ((const float4*)(y0 + (size_t)tt * HH))[tid];
                __syncthreads();
#pragma unroll
                for (int r = 0; r < 8; r++) {
                    float acc = dot128(w, ybuf + r * HH);
                    xo[(size_t)(tt + r) * GG + tid] = acc + bi;
                }
                __syncthreads();
            }
        }
    }
}

// ---------- Phase C: layer-1 recurrence + fused ReLU->FC epilogue ----------
__global__ void __launch_bounds__(384, 1)
k_layer1(const float* __restrict__ hidden,
         const float* __restrict__ w_hh1, const float* __restrict__ b_hh1,
         const float* __restrict__ fc_w, const float* __restrict__ fc_b,
         float* __restrict__ out, float* __restrict__ hT) {
    __shared__ __align__(16) float hsm[2][HH];
    __shared__ float s_z[HH], s_hn[HH], s_xn[HH];
    __shared__ float red[2][4];
    const int b = blockIdx.x, tid = threadIdx.x;
    const int warp = tid >> 5, lane = tid & 31;
    const int grp = warp / 3, role = warp - grp * 3;
    const int unit = (grp << 5) | lane;
    const int row = role * HH + unit;

    ull w[64];
    loadw(w, w_hh1 + row * HH);
    const float bh = b_hh1[row];
    const float fw = fc_w[unit];
    const float fcb = fc_b[0];

    float h_old = hidden[(size_t)BB * HH + (size_t)b * HH + unit];
    if (role == 0) hsm[0][unit] = h_old;
    __syncthreads();

    const float* xgp = g_xg1 + (size_t)b * TT * GG + row;
    float* outp = out + (size_t)b * TT;

    int cur = 0;
    float xv = xgp[0];
    float p = 0.f;
    for (int t = 0; t < TT; t++) {
        float acc = dot128(w, hsm[cur]) + bh;
        int tn = (t + 1 < TT) ? t + 1 : t;
        float xnext = xgp[(size_t)tn * GG];     // prefetch next step's x
        float pre = acc + xv;                   // role 0: r_pre
        if (role == 1) s_z[unit] = pre;
        else if (role == 2) { s_hn[unit] = acc; s_xn[unit] = xv; }
        asm volatile("bar.sync %0, 96;" :: "r"(grp + 1) : "memory");
        if (role == 0) {
            float r = sigfast(pre);
            float z = sigf(s_z[unit]);
            float n = tanha(fmaf(r, s_hn[unit], s_xn[unit]));
            h_old = (1.f - z) * n + z * h_old;
            hsm[cur ^ 1][unit] = h_old;
            p = fmaxf(h_old, 0.f) * fw;
        }
        __syncthreads();
        // Branchless butterfly; real p only on role-0 lanes. Off critical path.
        float q = p;
        q += __shfl_xor_sync(0xffffffffu, q, 16);
        q += __shfl_xor_sync(0xffffffffu, q, 8);
        q += __shfl_xor_sync(0xffffffffu, q, 4);
        q += __shfl_xor_sync(0xffffffffu, q, 2);
        q += __shfl_xor_sync(0xffffffffu, q, 1);
        if (role == 0 && lane == 0) red[t & 1][grp] = q;
        if (t > 0 && tid == 0) {
            const float* rd = red[(t - 1) & 1];
            outp[t - 1] = ((rd[0] + rd[1]) + (rd[2] + rd[3])) + fcb;
        }
        xv = xnext;
        cur ^= 1;
    }
    __syncthreads();
    if (tid == 0) {
        const float* rd = red[(TT - 1) & 1];
        outp[TT - 1] = ((rd[0] + rd[1]) + (rd[2] + rd[3])) + fcb;
    }
    if (role == 0) hT[(size_t)b * HH + unit] = h_old;
}

extern "C" void kernel_launch(void* const* d_in, const int* in_sizes, int n_in,
                              void* d_out, int out_size) {
    const float* data   = (const float*)d_in[0];
    const float* hidden = (const float*)d_in[1];
    const float* w_ih0  = (const float*)d_in[2];
    const float* w_hh0  = (const float*)d_in[3];
    const float* b_ih0  = (const float*)d_in[4];
    const float* b_hh0  = (const float*)d_in[5];
    const float* w_ih1  = (const float*)d_in[6];
    const float* w_hh1  = (const float*)d_in[7];
    const float* b_ih1  = (const float*)d_in[8];
    const float* b_hh1  = (const float*)d_in[9];
    const float* fc_w   = (const float*)d_in[10];
    const float* fc_b   = (const float*)d_in[11];

    float* out = (float*)d_out;
    float* hT0 = out + (size_t)BB * TT;        // hidden output, layer 0
    float* hT1 = hT0 + (size_t)BB * HH;        // hidden output, layer 1

    k_reset<<<2, 1024>>>();
    k_phaseAB<<<BB + NWORK, 384>>>(data, hidden, w_ih0, w_hh0, b_ih0, b_hh0,
                                   w_ih1, b_ih1, hT0);
    k_layer1<<<BB, 384>>>(hidden, w_hh1, b_hh1, fc_w, fc_b, out, hT1);
}

// round 5
// speedup vs baseline: 1.7479x; 1.0722x over previous
#include <cuda_runtime.h>

#define BB 64
#define TT 4096
#define HH 128
#define GG 384   /* 3H */
#define NWORK 84 /* B-worker CTAs; 64 + 84 = 148 = full wave-1 residency */

// Scratch (allocation-free rule: __device__ globals)
__device__ float g_y0[(size_t)BB * TT * HH];    // layer-0 outputs   128 MiB
__device__ float g_xg1[(size_t)BB * TT * GG];   // layer-1 ih gates  402 MiB
__device__ float g_y1[(size_t)BB * TT * HH];    // layer-1 outputs   128 MiB
__device__ int   g_flagA[BB * 32];              // y0 chunk ready (producer -> worker)
__device__ int   g_flagB[BB * 32];              // xg1 chunk ready (worker -> consumer)

typedef unsigned long long ull;

static __device__ __forceinline__ ull pk(float a, float b) {
    ull r; asm("mov.b64 %0, {%1, %2};" : "=l"(r) : "f"(a), "f"(b)); return r;
}
static __device__ __forceinline__ void upk(ull v, float& a, float& b) {
    asm("mov.b64 {%0, %1}, %2;" : "=f"(a), "=f"(b) : "l"(v));
}
// Packed fp32x2 FMA (Blackwell): 2 MACs per issue slot
static __device__ __forceinline__ void ffma2(ull& acc, ull a, ull b) {
    asm("fma.rn.f32x2 %0, %1, %2, %0;" : "+l"(acc) : "l"(a), "l"(b));
}
static __device__ __forceinline__ float red2(ull a, ull b) {
    float x0, x1, y0, y1; upk(a, x0, x1); upk(b, y0, y1);
    return (x0 + x1) + (y0 + y1);
}
static __device__ __forceinline__ float tanha(float x) {     // MUFU tanh
    float y; asm("tanh.approx.f32 %0, %1;" : "=f"(y) : "f"(x)); return y;
}
static __device__ __forceinline__ float sigfast(float x) {   // sigmoid via MUFU tanh
    return fmaf(0.5f, tanha(0.5f * x), 0.5f);
}
static __device__ __forceinline__ int ldacq(const int* p) {
    int v; asm volatile("ld.acquire.gpu.global.b32 %0, [%1];" : "=r"(v) : "l"(p) : "memory");
    return v;
}
static __device__ __forceinline__ void strel(int* p, int v) {
    asm volatile("st.release.gpu.global.b32 [%0], %1;" :: "l"(p), "r"(v) : "memory");
}

// Load one 128-float weight row into 64 packed register pairs.
static __device__ __forceinline__ void loadw(ull* w, const float* __restrict__ row) {
    const float4* r4 = (const float4*)row;
#pragma unroll
    for (int i = 0; i < 32; i++) {
        float4 v = r4[i];
        w[2 * i]     = pk(v.x, v.y);
        w[2 * i + 1] = pk(v.z, v.w);
    }
}

// dot(w_row[128], hsm[128]) with broadcast LDS.128 + packed FMA, 4 acc chains.
static __device__ __forceinline__ float dot128(const ull* w, const float* hsm) {
    const ulonglong2* h2 = (const ulonglong2*)hsm;
    ull a0 = 0, a1 = 0, a2 = 0, a3 = 0;
#pragma unroll
    for (int k = 0; k < 16; k++) {
        ulonglong2 p = h2[2 * k];
        ulonglong2 q = h2[2 * k + 1];
        ffma2(a0, w[4 * k + 0], p.x);
        ffma2(a1, w[4 * k + 1], p.y);
        ffma2(a2, w[4 * k + 2], q.x);
        ffma2(a3, w[4 * k + 3], q.y);
    }
    return red2(a0, a1) + red2(a2, a3);
}

__global__ void k_reset() {
    int i = blockIdx.x * 1024 + threadIdx.x;
    if (i < BB * 32) { g_flagA[i] = 0; g_flagB[i] = 0; }
}

// ===== Mega-kernel: 64 recurrence CTAs (layer0 then role-switch to layer1)
//       + 84 B-worker CTAs (xg1 = y0 @ w_ih1.T + b_ih1, chunk-streamed) =====
// Recurrence thread layout: warp=tid>>5, grp=warp/3, role=warp%3 (0=r,1=z,2=n)
// Group g owns hidden units [32g,32g+32); named barrier (g+1) over its 96 threads.
// h double-buffered in SMEM -> one block-wide barrier per timestep.
__global__ void __launch_bounds__(384, 1)
k_main(const float* __restrict__ data, const float* __restrict__ hidden,
       const float* __restrict__ w_ih0, const float* __restrict__ w_hh0,
       const float* __restrict__ b_ih0, const float* __restrict__ b_hh0,
       const float* __restrict__ w_ih1, const float* __restrict__ w_hh1,
       const float* __restrict__ b_ih1, const float* __restrict__ b_hh1,
       float* __restrict__ hT) {
    __shared__ __align__(16) float hsm[2][HH];
    __shared__ float s_z[HH], s_hn[HH], s_xn[HH];
    __shared__ __align__(16) float xbuf[512];
    __shared__ __align__(16) float ybuf[8 * HH];

    const int tid = threadIdx.x;

    if (blockIdx.x >= BB) {
        // ---------------- B-WORKER: xg1 = y0 @ w_ih1.T + b_ih1 ----------------
        const int wk = blockIdx.x - BB;
        ull w[64];
        loadw(w, w_ih1 + tid * HH);
        const float bi = b_ih1[tid];

        for (int task = wk; task < BB * 32; task += NWORK) {
            const int c = task >> 6, b = task & 63;   // chunk-major: fresh y0 in L2
            if (tid == 0) {
                const int* f = g_flagA + b * 32 + c;
                while (ldacq(f) == 0) __nanosleep(64);
            }
            __syncthreads();
            const float* y0 = g_y0 + ((size_t)b * TT + (size_t)c * 128) * HH;
            float* xo = g_xg1 + ((size_t)b * TT + (size_t)c * 128) * GG;
            for (int tt = 0; tt < 128; tt += 8) {
                if (tid < 256) ((float4*)ybuf)[tid] = ((const float4*)(y0 + (size_t)tt * HH))[tid];
                __syncthreads();
#pragma unroll
                for (int r = 0; r < 8; r++) {
                    float acc = dot128(w, ybuf + r * HH);
                    xo[(size_t)(tt + r) * GG + tid] = acc + bi;
                }
                __syncthreads();
            }
            if (tid == 0) strel(g_flagB + b * 32 + c, 1);
        }
        return;
    }

    const int warp = tid >> 5, lane = tid & 31;
    const int grp = warp / 3, role = warp - grp * 3;
    const int unit = (grp << 5) | lane;
    const int row = role * HH + unit;
    const int b = blockIdx.x;

    // ================= PHASE 1: layer-0 recurrence (producer) =================
    {
        ull w[64];
        loadw(w, w_hh0 + row * HH);
        const float wi = w_ih0[row], bi = b_ih0[row], bh = b_hh0[row];

        float h_old = hidden[(size_t)b * HH + unit];
        if (role == 0) hsm[0][unit] = h_old;
        __syncthreads();

        const float* xg = data + (size_t)b * TT;
        float* y0 = g_y0 + (size_t)b * TT * HH;
        int* fl = g_flagA + b * 32;

        int cur = 0;
        for (int t = 0; t < TT; t++) {
            if ((t & 511) == 0) {
                if (tid < 128) ((float4*)xbuf)[tid] = ((const float4*)(xg + t))[tid];
                __syncthreads();
            }
            const float x = xbuf[t & 511];
            float acc = dot128(w, hsm[cur]) + bh;
            float xi = fmaf(x, wi, bi);
            float pre = acc + xi;                   // role 0: r_pre
            if (role == 1) s_z[unit] = pre;
            else if (role == 2) { s_hn[unit] = acc; s_xn[unit] = xi; }
            asm volatile("bar.sync %0, 96;" :: "r"(grp + 1) : "memory");
            if (role == 0) {
                float r = sigfast(pre);
                float z = sigfast(s_z[unit]);
                float n = tanha(fmaf(r, s_hn[unit], s_xn[unit]));
                h_old = (1.f - z) * n + z * h_old;
                hsm[cur ^ 1][unit] = h_old;
                y0[(size_t)t * HH + unit] = h_old;  // ship to B-workers
            }
            __syncthreads();
            // chunk-granular publish: barrier + release store => visible
            if (((t & 127) == 127) && tid == 0) strel(fl + (t >> 7), 1);
            cur ^= 1;
        }
        if (role == 0) hT[(size_t)b * HH + unit] = h_old;
    }

    // ====== PHASE 2 (role-switch): layer-1 recurrence on the same CTA ======
    __syncthreads();
    {
        ull w[64];
        loadw(w, w_hh1 + row * HH);
        const float bh = b_hh1[row];

        float h_old = hidden[(size_t)BB * HH + (size_t)b * HH + unit];
        if (role == 0) hsm[0][unit] = h_old;   // ordered by first chunk's barrier

        const float* xgp = g_xg1 + (size_t)b * TT * GG + row;
        float* y1 = g_y1 + (size_t)b * TT * HH;

        int cur = 0;
        for (int c = 0; c < 32; c++) {
            if (tid == 0) {
                const int* f = g_flagB + b * 32 + c;
                while (ldacq(f) == 0) __nanosleep(64);
            }
            __syncthreads();
            float xv = xgp[(size_t)(c * 128) * GG];
            for (int tt = 0; tt < 128; tt++) {
                const int t = c * 128 + tt;
                float acc = dot128(w, hsm[cur]) + bh;
                // prefetch next x within the chunk (next chunk: after its flag)
                float xnext = (tt < 127) ? xgp[(size_t)(t + 1) * GG] : 0.f;
                float pre = acc + xv;               // role 0: r_pre
                if (role == 1) s_z[unit] = pre;
                else if (role == 2) { s_hn[unit] = acc; s_xn[unit] = xv; }
                asm volatile("bar.sync %0, 96;" :: "r"(grp + 1) : "memory");
                if (role == 0) {
                    float r = sigfast(pre);
                    float z = sigfast(s_z[unit]);
                    float n = tanha(fmaf(r, s_hn[unit], s_xn[unit]));
                    h_old = (1.f - z) * n + z * h_old;
                    hsm[cur ^ 1][unit] = h_old;
                    y1[(size_t)t * HH + unit] = h_old;   // FC done by tail kernel
                }
                __syncthreads();
                xv = xnext;
                cur ^= 1;
            }
        }
        if (role == 0) hT[(size_t)BB * HH + (size_t)b * HH + unit] = h_old;
    }
}

// ---------- Tail: out[b,t] = relu(y1[b,t,:]) . fc_w + fc_b  (memory-bound) ----------
__global__ void __launch_bounds__(256)
k_fc(const float* __restrict__ fc_w, const float* __restrict__ fc_b,
     float* __restrict__ out) {
    const int row = blockIdx.x * 8 + (threadIdx.x >> 5);   // row = b*TT + t
    const int lane = threadIdx.x & 31;
    float4 yv = ((const float4*)(g_y1 + (size_t)row * HH))[lane];
    float4 wv = ((const float4*)fc_w)[lane];
    float p = fmaxf(yv.x, 0.f) * wv.x + fmaxf(yv.y, 0.f) * wv.y
            + fmaxf(yv.z, 0.f) * wv.z + fmaxf(yv.w, 0.f) * wv.w;
    p += __shfl_xor_sync(0xffffffffu, p, 16);
    p += __shfl_xor_sync(0xffffffffu, p, 8);
    p += __shfl_xor_sync(0xffffffffu, p, 4);
    p += __shfl_xor_sync(0xffffffffu, p, 2);
    p += __shfl_xor_sync(0xffffffffu, p, 1);
    if (lane == 0) out[row] = p + fc_b[0];
}

extern "C" void kernel_launch(void* const* d_in, const int* in_sizes, int n_in,
                              void* d_out, int out_size) {
    const float* data   = (const float*)d_in[0];
    const float* hidden = (const float*)d_in[1];
    const float* w_ih0  = (const float*)d_in[2];
    const float* w_hh0  = (const float*)d_in[3];
    const float* b_ih0  = (const float*)d_in[4];
    const float* b_hh0  = (const float*)d_in[5];
    const float* w_ih1  = (const float*)d_in[6];
    const float* w_hh1  = (const float*)d_in[7];
    const float* b_ih1  = (const float*)d_in[8];
    const float* b_hh1  = (const float*)d_in[9];
    const float* fc_w   = (const float*)d_in[10];
    const float* fc_b   = (const float*)d_in[11];

    float* out = (float*)d_out;
    float* hT  = out + (size_t)BB * TT;   // [2,B,H] final hidden

    k_reset<<<2, 1024>>>();
    k_main<<<BB + NWORK, 384>>>(data, hidden, w_ih0, w_hh0, b_ih0, b_hh0,
                                w_ih1, w_hh1, b_ih1, b_hh1, hT);
    k_fc<<<BB * TT / 8, 256>>>(fc_w, fc_b, out);
}